// round 16
// baseline (speedup 1.0000x reference)
#include <cuda_runtime.h>
#include <cuda_fp16.h>
#include <math.h>
#include <stdint.h>

// ---------------------------------------------------------------------------
// DecoderLayer: B=2, S=2048, E=2048, NH=16, NKV=4, HD=128, FF=5632
// Round 15: R14 + RoPE fused into the qkv GEMM epilogue (MODE 4):
// Q CTAs write roped+scaled half to qh, K CTAs to kh, V CTAs to qkv buffer.
// rope_split_k deleted (kernel + 41MB of traffic).
// ---------------------------------------------------------------------------

#define B_    2
#define S_    2048
#define E_    2048
#define NH_   16
#define NKV_  4
#define HD_   128
#define FF_   5632
#define T_    (B_ * S_)
#define QKV_N ((NH_ + 2 * NKV_) * HD_)  // 3072
#define QSCALE 0.022097086912079608f   // 1/sqrt(2048)

// scratch (device globals; allocation-free)
__device__ __half g_qkvh [(size_t)T_ * QKV_N];   // only V region written
__device__ float  g_h    [(size_t)T_ * E_];
__device__ __half g_hnorm[(size_t)T_ * E_];
__device__ __half g_qh   [(size_t)B_ * NH_  * S_ * HD_];
__device__ __half g_kh   [(size_t)B_ * NKV_ * S_ * HD_];
__device__ __half g_vth  [(size_t)B_ * NKV_ * HD_ * S_];  // [b][h][d][s]
__device__ __half g_attnh[(size_t)T_ * E_];
__device__ __half g_ffh  [(size_t)T_ * FF_];
__device__ __half g_wqkvh[(size_t)QKV_N * E_];
__device__ __half g_wfch [(size_t)E_ * E_];
__device__ __half g_w1h  [(size_t)FF_ * E_];
__device__ __half g_w2h  [(size_t)FF_ * E_];
__device__ __half g_w3h  [(size_t)E_ * FF_];

// ---------------------------------------------------------------------------
__device__ __forceinline__ uint32_t smem_u32(const void* p) {
    uint32_t a;
    asm("{ .reg .u64 t; cvta.to.shared.u64 t, %1; cvt.u32.u64 %0, t; }"
        : "=r"(a) : "l"(p));
    return a;
}
__device__ __forceinline__ uint32_t packh2(float a, float b) {
    __half2 h = __floats2half2_rn(a, b);
    return *reinterpret_cast<uint32_t*>(&h);
}
__device__ __forceinline__ void cpa16(uint32_t dst, const void* src) {
    asm volatile("cp.async.cg.shared.global [%0], [%1], 16;"
                 :: "r"(dst), "l"(src) : "memory");
}
#define CP_COMMIT() asm volatile("cp.async.commit_group;" ::: "memory")
#define CP_WAIT_0() asm volatile("cp.async.wait_group 0;" ::: "memory")
#define CP_WAIT_1() asm volatile("cp.async.wait_group 1;" ::: "memory")

__device__ __forceinline__ void mma_f16(float* c, const uint32_t* a,
                                        uint32_t b0, uint32_t b1) {
    asm volatile(
        "mma.sync.aligned.m16n8k16.row.col.f32.f16.f16.f32 "
        "{%0,%1,%2,%3}, {%4,%5,%6,%7}, {%8,%9}, {%0,%1,%2,%3};"
        : "+f"(c[0]), "+f"(c[1]), "+f"(c[2]), "+f"(c[3])
        : "r"(a[0]), "r"(a[1]), "r"(a[2]), "r"(a[3]), "r"(b0), "r"(b1));
}
__device__ __forceinline__ void ldsm_x4(uint32_t& r0, uint32_t& r1,
                                        uint32_t& r2, uint32_t& r3,
                                        uint32_t addr) {
    asm volatile("ldmatrix.sync.aligned.m8n8.x4.shared.b16 {%0,%1,%2,%3}, [%4];"
                 : "=r"(r0), "=r"(r1), "=r"(r2), "=r"(r3) : "r"(addr));
}

// ---------------------------------------------------------------------------
// Segmented fp32 -> fp16 weight conversion, 4 float4 per thread (ILP-4).
// ---------------------------------------------------------------------------
#define CVT_B0 1536
#define CVT_B1 (CVT_B0 + 1024)    // 2560
#define CVT_B2 (CVT_B1 + 2816)    // 5376
#define CVT_B3 (CVT_B2 + 2816)    // 8192
#define CVT_B4 (CVT_B3 + 2816)    // 11008

__global__ void __launch_bounds__(256) cvt_all_k(const float* __restrict__ wqkv,
                                                 const float* __restrict__ wfc,
                                                 const float* __restrict__ w1,
                                                 const float* __restrict__ w2,
                                                 const float* __restrict__ w3,
                                                 __half* __restrict__ dqkv,
                                                 __half* __restrict__ dfc,
                                                 __half* __restrict__ d1,
                                                 __half* __restrict__ d2,
                                                 __half* __restrict__ d3) {
    int bx = blockIdx.x;
    const float* s; __half* d; int sb;
    if (bx < CVT_B0)      { s = wqkv; d = dqkv; sb = bx; }
    else if (bx < CVT_B1) { s = wfc;  d = dfc;  sb = bx - CVT_B0; }
    else if (bx < CVT_B2) { s = w1;   d = d1;   sb = bx - CVT_B1; }
    else if (bx < CVT_B3) { s = w2;   d = d2;   sb = bx - CVT_B2; }
    else                  { s = w3;   d = d3;   sb = bx - CVT_B3; }
    int i0 = sb * 1024 + threadIdx.x;
    float4 v[4];
    #pragma unroll
    for (int j = 0; j < 4; j++) v[j] = ((const float4*)s)[i0 + j * 256];
    #pragma unroll
    for (int j = 0; j < 4; j++) {
        uint2 o;
        o.x = packh2(v[j].x, v[j].y);
        o.y = packh2(v[j].z, v[j].w);
        ((uint2*)d)[i0 + j * 256] = o;
    }
}

// ---------------------------------------------------------------------------
// RMSNorm: fp32 in, fp16 out
// ---------------------------------------------------------------------------
__global__ void __launch_bounds__(256) rmsnorm_k(const float* __restrict__ x,
                                                 const float* __restrict__ w,
                                                 __half* __restrict__ o) {
    size_t base = (size_t)blockIdx.x * E_;
    int tid = threadIdx.x;
    float4 v0 = *(const float4*)(x + base + tid * 8);
    float4 v1 = *(const float4*)(x + base + tid * 8 + 4);
    float ss = v0.x*v0.x + v0.y*v0.y + v0.z*v0.z + v0.w*v0.w
             + v1.x*v1.x + v1.y*v1.y + v1.z*v1.z + v1.w*v1.w;
    #pragma unroll
    for (int off = 16; off; off >>= 1) ss += __shfl_xor_sync(0xffffffffu, ss, off);
    __shared__ float ws[8];
    if ((tid & 31) == 0) ws[tid >> 5] = ss;
    __syncthreads();
    float tot = ws[0] + ws[1] + ws[2] + ws[3] + ws[4] + ws[5] + ws[6] + ws[7];
    float sc = rsqrtf(tot * (1.0f / E_) + 1e-5f);
    float4 w0 = *(const float4*)(w + tid * 8);
    float4 w1w = *(const float4*)(w + tid * 8 + 4);
    uint4 r;
    r.x = packh2(v0.x*sc*w0.x,  v0.y*sc*w0.y);
    r.y = packh2(v0.z*sc*w0.z,  v0.w*sc*w0.w);
    r.z = packh2(v1.x*sc*w1w.x, v1.y*sc*w1w.y);
    r.w = packh2(v1.z*sc*w1w.z, v1.w*sc*w1w.w);
    *(uint4*)(o + base + tid * 8) = r;
}

// ---------------------------------------------------------------------------
// fp16 GEMM: C[M,N] = A[M,K]*B[N,K]^T. CTA tile 256 x BN, BK=64, 3-stage.
// MODE 1: C(f32) = R + A·B^T              (BN=128)
// MODE 2: C(f16) = silu(A·B^T)*(A·B2^T)   (BN=64; smem B rows 64..127 = B2)
// MODE 3: C(f16) = A·B^T                  (BN=128)
// MODE 4: qkv+RoPE epilogue               (BN=128; R=freqs, O1=qh, O2=kh)
//         head hh = blockIdx.x: <16 -> Q roped+scaled to O1,
//         16..19 -> K roped to O2, 20..23 -> raw half to Cout (V region).
// 8 warps (4M x 2N), warp tile 64x64. Fragments via ldmatrix.x4.
// ---------------------------------------------------------------------------
#define GSTAGE 49152                    // (256 A rows + 128 B rows) * 128B
#define GEMM_SMEM (3 * GSTAGE)          // 147456

template <int MODE>
__global__ void __launch_bounds__(256) tgemm_k(const __half* __restrict__ A,
                                               const __half* __restrict__ Bm,
                                               const __half* __restrict__ B2,
                                               const float* __restrict__ R,
                                               void* __restrict__ Cout,
                                               __half* __restrict__ O1,
                                               __half* __restrict__ O2,
                                               int M, int N, int K) {
    extern __shared__ char sm[];
    constexpr int BN = (MODE == 2) ? 64 : 128;
    constexpr int NT = (MODE == 2) ? 4 : 8;   // n-tiles per warp per B matrix

    const int tid = threadIdx.x;
    const int m0 = blockIdx.y * 256, n0 = blockIdx.x * BN;
    const uint32_t smb = smem_u32(sm);

    // loader tables: 12 x (smem offset, global ptr)
    uint32_t so[12];
    const __half* gp[12];
    #pragma unroll
    for (int j = 0; j < 12; j++) {
        int ci = tid + j * 256;
        int row = ci >> 3, ch = ci & 7;
        so[j] = (uint32_t)(row * 128 + ((ch ^ (row & 7)) << 4));
        if (row < 256) {
            gp[j] = A + (size_t)(m0 + row) * K + ch * 8;
        } else {
            int br = row - 256;
            if (MODE == 2)
                gp[j] = ((br < 64) ? (Bm + (size_t)(n0 + br) * K)
                                   : (B2 + (size_t)(n0 + br - 64) * K)) + ch * 8;
            else
                gp[j] = Bm + (size_t)(n0 + br) * K + ch * 8;
        }
    }

    auto load_chunk = [&](int st, int c) {
        uint32_t base = smb + st * GSTAGE;
        #pragma unroll
        for (int j = 0; j < 12; j++)
            cpa16(base + so[j], gp[j] + c * 64);
        CP_COMMIT();
    };

    const int wid = tid >> 5, lane = tid & 31;
    const int gid = lane >> 2, tg = lane & 3;
    const int wm = wid >> 1, wn = wid & 1;
    const int l7 = lane & 7;
    const int lhi = lane >> 4;            // 0/1
    const int lbit3 = (lane >> 3) & 1;    // 0/1

    // ldmatrix row-byte offsets (swizzle XOR applied per ks)
    uint32_t rowA[4], rowB[NT / 2];
    #pragma unroll
    for (int mt = 0; mt < 4; mt++)
        rowA[mt] = (uint32_t)((wm * 64 + mt * 16 + (lane & 15)) * 128);
    #pragma unroll
    for (int p = 0; p < NT / 2; p++)
        rowB[p] = (uint32_t)((wn * (NT * 8) + (2 * p + lhi) * 8 + l7) * 128);
    uint32_t rowB2[(MODE == 2) ? 2 : 1];
    if (MODE == 2) {
        #pragma unroll
        for (int p = 0; p < 2; p++)
            rowB2[p] = (uint32_t)((64 + wn * 32 + (2 * p + lhi) * 8 + l7) * 128);
    }

    float c1[4][NT][4];
    float c2[(MODE == 2) ? 4 : 1][(MODE == 2) ? NT : 1][4];
    #pragma unroll
    for (int mt = 0; mt < 4; mt++)
        #pragma unroll
        for (int nt = 0; nt < NT; nt++)
            #pragma unroll
            for (int q = 0; q < 4; q++) {
                c1[mt][nt][q] = 0.f;
                if (MODE == 2) c2[mt][nt][q] = 0.f;
            }

    const int NC = K >> 6;
    load_chunk(0, 0);
    load_chunk(1, 1);

    for (int c = 0; c < NC; c++) {
        if (c + 1 < NC) CP_WAIT_1(); else CP_WAIT_0();
        __syncthreads();
        if (c + 2 < NC) load_chunk((c + 2) % 3, c + 2);

        const uint32_t ab = smb + (c % 3) * GSTAGE;
        const uint32_t bb = ab + 32768;
        #pragma unroll
        for (int ks = 0; ks < 4; ks++) {
            const uint32_t swA = (uint32_t)(((2 * ks + lhi)   ^ l7) << 4);
            const uint32_t swB = (uint32_t)(((2 * ks + lbit3) ^ l7) << 4);
            uint32_t af[4][4];
            #pragma unroll
            for (int mt = 0; mt < 4; mt++)
                ldsm_x4(af[mt][0], af[mt][1], af[mt][2], af[mt][3],
                        ab + rowA[mt] + swA);
            uint32_t bf[NT][2];
            #pragma unroll
            for (int p = 0; p < NT / 2; p++)
                ldsm_x4(bf[2 * p][0], bf[2 * p][1], bf[2 * p + 1][0],
                        bf[2 * p + 1][1], bb + rowB[p] + swB);
            #pragma unroll
            for (int mt = 0; mt < 4; mt++)
                #pragma unroll
                for (int nt = 0; nt < NT; nt++)
                    mma_f16(c1[mt][nt], af[mt], bf[nt][0], bf[nt][1]);
            if (MODE == 2) {
                uint32_t bf2[NT][2];
                #pragma unroll
                for (int p = 0; p < 2; p++)
                    ldsm_x4(bf2[2 * p][0], bf2[2 * p][1], bf2[2 * p + 1][0],
                            bf2[2 * p + 1][1], bb + rowB2[p] + swB);
                #pragma unroll
                for (int mt = 0; mt < 4; mt++)
                    #pragma unroll
                    for (int nt = 0; nt < NT; nt++)
                        mma_f16(c2[mt][nt], af[mt], bf2[nt][0], bf2[nt][1]);
            }
        }
    }

    // epilogue
    #pragma unroll
    for (int mt = 0; mt < 4; mt++) {
        #pragma unroll
        for (int half = 0; half < 2; half++) {
            size_t row = (size_t)(m0 + wm * 64 + mt * 16 + gid + half * 8);
            #pragma unroll
            for (int nt = 0; nt < NT; nt++) {
                int col = n0 + wn * (NT * 8) + nt * 8 + tg * 2;
                float v0 = c1[mt][nt][half * 2 + 0];
                float v1 = c1[mt][nt][half * 2 + 1];
                if (MODE == 2) {
                    float u0 = c2[mt][nt][half * 2 + 0];
                    float u1 = c2[mt][nt][half * 2 + 1];
                    v0 = (v0 / (1.0f + __expf(-v0))) * u0;
                    v1 = (v1 / (1.0f + __expf(-v1))) * u1;
                    *(uint32_t*)((__half*)Cout + row * N + col) = packh2(v0, v1);
                } else if (MODE == 3) {
                    *(uint32_t*)((__half*)Cout + row * N + col) = packh2(v0, v1);
                } else if (MODE == 4) {
                    const int hh = blockIdx.x;   // head: n0 = hh*128
                    if (hh < 20) {
                        int d = wn * 64 + nt * 8 + tg * 2;
                        int s = (int)(row & 2047);
                        int bb2 = (int)(row >> 11);
                        float2 f = *(const float2*)(R + (size_t)s * HD_ + d);
                        float r0 = v0 * f.x - v1 * f.y;
                        float r1 = v1 * f.x + v0 * f.y;
                        if (hh < 16) {
                            r0 *= QSCALE; r1 *= QSCALE;
                            *(uint32_t*)(O1 + ((size_t)(bb2 * NH_ + hh) * S_ + s) * HD_ + d)
                                = packh2(r0, r1);
                        } else {
                            *(uint32_t*)(O2 + ((size_t)(bb2 * NKV_ + hh - 16) * S_ + s) * HD_ + d)
                                = packh2(r0, r1);
                        }
                    } else {
                        *(uint32_t*)((__half*)Cout + row * N + col) = packh2(v0, v1);
                    }
                } else {
                    float2 res = *(const float2*)(R + row * N + col);
                    v0 += res.x; v1 += res.y;
                    *(float2*)((float*)Cout + row * N + col) = make_float2(v0, v1);
                }
            }
        }
    }
}

// ---------------------------------------------------------------------------
// V transpose: qkv half -> vt half [b][h][d][s], 32x32 smem tiles.
// ---------------------------------------------------------------------------
__global__ void __launch_bounds__(256) vtrans_k(const __half* __restrict__ qkv,
                                                __half* __restrict__ vt) {
    __shared__ __half tsm[32][40];
    int bh = blockIdx.z, b = bh >> 2, h = bh & 3;
    int s0 = blockIdx.x * 32, d0 = blockIdx.y * 32;
    int tx = threadIdx.x & 31, ty = threadIdx.x >> 5;  // 32 x 8
    #pragma unroll
    for (int i = 0; i < 4; i++) {
        int s = s0 + ty + i * 8;
        tsm[ty + i * 8][tx] =
            qkv[((size_t)(b * S_ + s)) * QKV_N + (NH_ + NKV_) * HD_ + h * HD_ + d0 + tx];
    }
    __syncthreads();
    #pragma unroll
    for (int i = 0; i < 4; i++) {
        int d = d0 + ty + i * 8;
        vt[((size_t)(b * NKV_ + h) * HD_ + d) * S_ + s0 + tx] = tsm[tx][ty + i * 8];
    }
}

// ---------------------------------------------------------------------------
// Flash attention on fp16 mma. BM=128, BN=64 kv tiles, 3-stage cp.async.
// LPT order; K/Vt fragments via ldmatrix.x4.
// ---------------------------------------------------------------------------
#define AT_BLK 16384
#define AT_STAGE (2 * AT_BLK)
#define ATT_SMEM (3 * AT_STAGE)   // 98304

__global__ void __launch_bounds__(256, 1) attn_k(const __half* __restrict__ Q,
                                                 const __half* __restrict__ K,
                                                 const __half* __restrict__ Vt,
                                                 __half* __restrict__ O) {
    extern __shared__ char smc[];
    const uint32_t smb = smem_u32(smc);
    const int tid = threadIdx.x;
    const int wq = tid >> 5, lane = tid & 31;
    const int gid = lane >> 2, tg = lane & 3;
    const int l7 = lane & 7;
    const int lhi = lane >> 4;
    const int lbit3 = (lane >> 3) & 1;
    const int qt = gridDim.x - 1 - blockIdx.x;   // LPT: heavy tiles first
    const int hh = blockIdx.y, b = blockIdx.z;
    const int q0 = qt * 128;

    const __half* Qp = Q  + (size_t)(b * NH_  + hh)        * S_ * HD_;
    const __half* Kp = K  + (size_t)(b * NKV_ + (hh >> 2)) * S_ * HD_;
    const __half* Vp = Vt + (size_t)(b * NKV_ + (hh >> 2)) * HD_ * S_;

    const int ra = q0 + wq * 16 + gid;   // rows ra, ra+8

    uint32_t qa[8][4];
    #pragma unroll
    for (int kc = 0; kc < 8; kc++) {
        const __half* p0 = Qp + (size_t)ra * HD_ + kc * 16 + 2 * tg;
        qa[kc][0] = *(const uint32_t*)(p0);
        qa[kc][1] = *(const uint32_t*)(p0 + 8 * HD_);
        qa[kc][2] = *(const uint32_t*)(p0 + 8);
        qa[kc][3] = *(const uint32_t*)(p0 + 8 * HD_ + 8);
    }

    const int lrow = tid >> 1;
    const int ci0 = (tid & 1) * 4;
    uint32_t dsto[4];
    #pragma unroll
    for (int i = 0; i < 4; i++)
        dsto[i] = (uint32_t)(lrow * 128 + (((ci0 + i) ^ (lrow & 7)) << 4));
    const __half* Kg = Kp + (size_t)(lrow & 63) * HD_ + (lrow >> 6) * 64 + ci0 * 8;
    const __half* Vg = Vp + (size_t)lrow * S_ + ci0 * 8;

    auto load_tile = [&](int st, int kt) {
        int k0 = kt * 64;
        uint32_t kb = smb + st * AT_STAGE;
        uint32_t vb = kb + AT_BLK;
        const __half* kg = Kg + (size_t)k0 * HD_;
        const __half* vg = Vg + k0;
        #pragma unroll
        for (int i = 0; i < 4; i++) {
            cpa16(kb + dsto[i], kg + i * 8);
            cpa16(vb + dsto[i], vg + i * 8);
        }
        CP_COMMIT();
    };

    uint32_t rowKV[8];
    #pragma unroll
    for (int p = 0; p < 8; p++)
        rowKV[p] = (uint32_t)(((2 * p + lhi) * 8 + l7) * 128);

    float o[16][4];
    #pragma unroll
    for (int dt = 0; dt < 16; dt++)
        #pragma unroll
        for (int q = 0; q < 4; q++) o[dt][q] = 0.f;
    float mA = -1e30f, mB = -1e30f, lA = 0.f, lB = 0.f;

    const int nkt = 2 * qt + 2;
    load_tile(0, 0);
    load_tile(1, 1);

    for (int kt = 0; kt < nkt; kt++) {
        if (kt + 1 < nkt) CP_WAIT_1(); else CP_WAIT_0();
        __syncthreads();
        if (kt + 2 < nkt) load_tile((kt + 2) % 3, kt + 2);

        const uint32_t kb = smb + (kt % 3) * AT_STAGE;
        const uint32_t vb = kb + AT_BLK;
        const int k0 = kt * 64;

        float s[8][4];
        #pragma unroll
        for (int nt = 0; nt < 8; nt++)
            #pragma unroll
            for (int q = 0; q < 4; q++) s[nt][q] = 0.f;
        #pragma unroll
        for (int kc = 0; kc < 8; kc++) {
            const uint32_t kb2 = kb + (uint32_t)((kc >> 2) * 8192);
            const uint32_t swK = (uint32_t)(((2 * (kc & 3) + lbit3) ^ l7) << 4);
            #pragma unroll
            for (int p = 0; p < 4; p++) {
                uint32_t b0, b1, b2, b3;
                ldsm_x4(b0, b1, b2, b3, kb2 + rowKV[p] + swK);
                mma_f16(s[2 * p],     qa[kc], b0, b1);
                mma_f16(s[2 * p + 1], qa[kc], b2, b3);
            }
        }

        float mtA = -1e30f, mtB = -1e30f;
        #pragma unroll
        for (int nt = 0; nt < 8; nt++) {
            int c0 = k0 + nt * 8 + tg * 2, c1 = c0 + 1;
            if (c0 > ra)     s[nt][0] = -1e30f;
            if (c1 > ra)     s[nt][1] = -1e30f;
            if (c0 > ra + 8) s[nt][2] = -1e30f;
            if (c1 > ra + 8) s[nt][3] = -1e30f;
            mtA = fmaxf(mtA, fmaxf(s[nt][0], s[nt][1]));
            mtB = fmaxf(mtB, fmaxf(s[nt][2], s[nt][3]));
        }
        mtA = fmaxf(mtA, __shfl_xor_sync(0xffffffffu, mtA, 1));
        mtA = fmaxf(mtA, __shfl_xor_sync(0xffffffffu, mtA, 2));
        mtB = fmaxf(mtB, __shfl_xor_sync(0xffffffffu, mtB, 1));
        mtB = fmaxf(mtB, __shfl_xor_sync(0xffffffffu, mtB, 2));

        float mnA = fmaxf(mA, mtA), mnB = fmaxf(mB, mtB);
        float facA = __expf(mA - mnA), facB = __expf(mB - mnB);
        float lsA = 0.f, lsB = 0.f;
        #pragma unroll
        for (int nt = 0; nt < 8; nt++) {
            s[nt][0] = __expf(s[nt][0] - mnA);
            s[nt][1] = __expf(s[nt][1] - mnA);
            s[nt][2] = __expf(s[nt][2] - mnB);
            s[nt][3] = __expf(s[nt][3] - mnB);
            lsA += s[nt][0] + s[nt][1];
            lsB += s[nt][2] + s[nt][3];
        }
        lsA += __shfl_xor_sync(0xffffffffu, lsA, 1);
        lsA += __shfl_xor_sync(0xffffffffu, lsA, 2);
        lsB += __shfl_xor_sync(0xffffffffu, lsB, 1);
        lsB += __shfl_xor_sync(0xffffffffu, lsB, 2);
        lA = lA * facA + lsA;  mA = mnA;
        lB = lB * facB + lsB;  mB = mnB;

        #pragma unroll
        for (int dt = 0; dt < 16; dt++) {
            o[dt][0] *= facA; o[dt][1] *= facA;
            o[dt][2] *= facB; o[dt][3] *= facB;
        }

        #pragma unroll
        for (int j = 0; j < 4; j++) {
            uint32_t aa[4];
            aa[0] = packh2(s[2 * j][0],     s[2 * j][1]);
            aa[1] = packh2(s[2 * j][2],     s[2 * j][3]);
            aa[2] = packh2(s[2 * j + 1][0], s[2 * j + 1][1]);
            aa[3] = packh2(s[2 * j + 1][2], s[2 * j + 1][3]);
            const uint32_t swV = (uint32_t)(((2 * j + lbit3) ^ l7) << 4);
            #pragma unroll
            for (int p = 0; p < 8; p++) {
                uint32_t b0, b1, b2, b3;
                ldsm_x4(b0, b1, b2, b3, vb + rowKV[p] + swV);
                mma_f16(o[2 * p],     aa, b0, b1);
                mma_f16(o[2 * p + 1], aa, b2, b3);
            }
        }
        __syncthreads();
    }

    float iA = 1.0f / lA, iB = 1.0f / lB;
    __half* OpA = O + (((size_t)b * S_ + ra)     * NH_ + hh) * HD_;
    __half* OpB = O + (((size_t)b * S_ + ra + 8) * NH_ + hh) * HD_;
    #pragma unroll
    for (int dt = 0; dt < 16; dt++) {
        int d = dt * 8 + tg * 2;
        *(uint32_t*)(OpA + d) = packh2(o[dt][0] * iA, o[dt][1] * iA);
        *(uint32_t*)(OpB + d) = packh2(o[dt][2] * iB, o[dt][3] * iB);
    }
}

// ---------------------------------------------------------------------------
// launch
// ---------------------------------------------------------------------------
extern "C" void kernel_launch(void* const* d_in, const int* in_sizes, int n_in,
                              void* d_out, int out_size) {
    const float* x     = (const float*)d_in[0];
    const float* freqs = (const float*)d_in[2];
    const float* w_qkv = (const float*)d_in[4];
    const float* w_fc  = (const float*)d_in[5];
    const float* w1    = (const float*)d_in[6];
    const float* w2    = (const float*)d_in[7];
    const float* w3    = (const float*)d_in[8];
    const float* anw   = (const float*)d_in[9];
    const float* fnw   = (const float*)d_in[10];
    float* out = (float*)d_out;

    float *h;
    __half *qkvh, *hnorm, *qh, *kh, *vth, *attnh, *ffh;
    __half *wqkvh, *wfch, *w1h, *w2h, *w3h;
    cudaGetSymbolAddress((void**)&qkvh,  g_qkvh);
    cudaGetSymbolAddress((void**)&h,     g_h);
    cudaGetSymbolAddress((void**)&hnorm, g_hnorm);
    cudaGetSymbolAddress((void**)&qh,    g_qh);
    cudaGetSymbolAddress((void**)&kh,    g_kh);
    cudaGetSymbolAddress((void**)&vth,   g_vth);
    cudaGetSymbolAddress((void**)&attnh, g_attnh);
    cudaGetSymbolAddress((void**)&ffh,   g_ffh);
    cudaGetSymbolAddress((void**)&wqkvh, g_wqkvh);
    cudaGetSymbolAddress((void**)&wfch,  g_wfch);
    cudaGetSymbolAddress((void**)&w1h,   g_w1h);
    cudaGetSymbolAddress((void**)&w2h,   g_w2h);
    cudaGetSymbolAddress((void**)&w3h,   g_w3h);

    static bool attr_done = false;
    if (!attr_done) {
        cudaFuncSetAttribute(tgemm_k<1>, cudaFuncAttributeMaxDynamicSharedMemorySize, GEMM_SMEM);
        cudaFuncSetAttribute(tgemm_k<2>, cudaFuncAttributeMaxDynamicSharedMemorySize, GEMM_SMEM);
        cudaFuncSetAttribute(tgemm_k<4>, cudaFuncAttributeMaxDynamicSharedMemorySize, GEMM_SMEM);
        cudaFuncSetAttribute(attn_k, cudaFuncAttributeMaxDynamicSharedMemorySize, ATT_SMEM);
        attr_done = true;
    }

    // 0. weights -> fp16 (single segmented launch, ILP-4)
    cvt_all_k<<<CVT_B4, 256>>>(w_qkv, w_fc, w1, w2, w3,
                               wqkvh, wfch, w1h, w2h, w3h);

    // 1. h_norm = half(rmsnorm(x) * attn_norm_w)
    rmsnorm_k<<<T_, 256>>>(x, anw, hnorm);
    // 2. qkv GEMM + fused RoPE: Q->qh (roped+scaled), K->kh (roped), V->qkvh
    tgemm_k<4><<<dim3(QKV_N / 128, T_ / 256), 256, GEMM_SMEM>>>(
        hnorm, wqkvh, nullptr, freqs, qkvh, qh, kh, T_, QKV_N, E_);
    // 3. V transpose (half, [b][h][d][s])
    vtrans_k<<<dim3(S_ / 32, HD_ / 32, B_ * NKV_), 256>>>(qkvh, vth);
    // 4. causal flash attention (fp16 mma, f32 softmax, LPT order)
    attn_k<<<dim3(S_ / 128, NH_, B_), 256, ATT_SMEM>>>(qh, kh, vth, attnh);
    // 5. h(f32) = x + attnh @ w_fc^T
    tgemm_k<1><<<dim3(E_ / 128, T_ / 256), 256, GEMM_SMEM>>>(
        attnh, wfch, nullptr, x, h, nullptr, nullptr, T_, E_, E_);
    // 6. g = half(rmsnorm(h) * ff_norm_w)
    rmsnorm_k<<<T_, 256>>>(h, fnw, hnorm);
    // 7. ffh(f16) = silu(g @ w1^T) * (g @ w2^T)
    tgemm_k<2><<<dim3(FF_ / 64, T_ / 256), 256, GEMM_SMEM>>>(
        hnorm, w1h, w2h, nullptr, ffh, nullptr, nullptr, T_, FF_, E_);
    // 8. out(f32) = h + ffh @ w3^T
    tgemm_k<1><<<dim3(E_ / 128, T_ / 256), 256, GEMM_SMEM>>>(
        ffh, w3h, nullptr, h, out, nullptr, nullptr, T_, E_, FF_);
}